// round 5
// baseline (speedup 1.0000x reference)
#include <cuda_runtime.h>
#include <cuda_bf16.h>
#include <math.h>
#include <cstdint>

// Problem dims (fixed per reference)
#define Bz 64
#define Tz 512
#define Dz 2048
#define Hz 512
#define BT (Bz * Tz)          // 32768
#define NBLK 4                // H/128 h-blocks for partial scores

// Scratch (__device__ globals; allocation-free rule)
__device__ float g_uh[Bz * Hz];
__device__ float g_partial[NBLK * BT];
__device__ float g_att[BT];
__device__ __nv_bfloat16 g_WaT[Hz * Dz];   // Wa transposed -> [H, D] bf16
__device__ float g_wpart[4 * Bz * Dz];

// ---------------------------------------------------------------------------
// helpers
// ---------------------------------------------------------------------------
__device__ __forceinline__ uint32_t smem_u32(const void* p) {
    uint32_t a;
    asm("{ .reg .u64 t; cvta.to.shared.u64 t, %1; cvt.u32.u64 %0, t; }"
        : "=r"(a) : "l"(p));
    return a;
}

#define SWZ(o) ((o) ^ (((o) >> 3) & 0x70))

__device__ __forceinline__ void ldsm4(uint32_t* a, uint32_t addr) {
    asm volatile("ldmatrix.sync.aligned.m8n8.x4.shared.b16 {%0,%1,%2,%3}, [%4];"
                 : "=r"(a[0]), "=r"(a[1]), "=r"(a[2]), "=r"(a[3]) : "r"(addr));
}
__device__ __forceinline__ void mma16816(float* c, const uint32_t* a,
                                         const uint32_t* b) {
    asm volatile(
        "mma.sync.aligned.m16n8k16.row.col.f32.bf16.bf16.f32 "
        "{%0,%1,%2,%3}, {%4,%5,%6,%7}, {%8,%9}, {%0,%1,%2,%3};"
        : "+f"(c[0]), "+f"(c[1]), "+f"(c[2]), "+f"(c[3])
        : "r"(a[0]), "r"(a[1]), "r"(a[2]), "r"(a[3]), "r"(b[0]), "r"(b[1]));
}
__device__ __forceinline__ float tanh_fast(float x) {
    float y;
    asm("tanh.approx.f32 %0, %1;" : "=f"(y) : "f"(x));
    return y;
}
__device__ __forceinline__ void cp16(uint32_t dst, const void* src) {
    asm volatile("cp.async.cg.shared.global [%0], [%1], 16;"
                 :: "r"(dst), "l"(src));
}
#define CP_COMMIT() asm volatile("cp.async.commit_group;" ::: "memory")
#define CP_WAIT(n)  asm volatile("cp.async.wait_group %0;" :: "n"(n) : "memory")

// ---------------------------------------------------------------------------
// Kernel 0: WaT[n][k] = bf16(Wa[k][n])
// ---------------------------------------------------------------------------
__global__ void transpose_kernel(const float* __restrict__ Wa,
                                 __nv_bfloat16* __restrict__ WaT) {
    __shared__ float tile[32][33];
    const int k0 = blockIdx.x * 32, n0 = blockIdx.y * 32;
    for (int i = threadIdx.y; i < 32; i += 8)
        tile[i][threadIdx.x] = Wa[(size_t)(k0 + i) * Hz + n0 + threadIdx.x];
    __syncthreads();
    for (int i = threadIdx.y; i < 32; i += 8)
        WaT[(size_t)(n0 + i) * Dz + k0 + threadIdx.x] =
            __float2bfloat16(tile[threadIdx.x][i]);
}

// ---------------------------------------------------------------------------
// Kernel 1: Uh[b,h] = sum_d text[b,d] * Ua[d,h] + ba[h]   (fp32)
// ---------------------------------------------------------------------------
__global__ void uh_kernel(const float* __restrict__ text,
                          const float* __restrict__ Ua,
                          const float* __restrict__ ba,
                          float* __restrict__ uh) {
    const int h  = blockIdx.x * 128 + threadIdx.x;
    const int b0 = blockIdx.y * 8;
    float acc[8] = {0.f, 0.f, 0.f, 0.f, 0.f, 0.f, 0.f, 0.f};
    __shared__ float ts[8][32];

    for (int d0 = 0; d0 < Dz; d0 += 32) {
        for (int v = threadIdx.x; v < 8 * 32; v += 128) {
            int i = v >> 5, k = v & 31;
            ts[i][k] = text[(b0 + i) * Dz + d0 + k];
        }
        __syncthreads();
        #pragma unroll
        for (int k = 0; k < 32; k++) {
            float u = Ua[(size_t)(d0 + k) * Hz + h];
            #pragma unroll
            for (int i = 0; i < 8; i++) acc[i] = fmaf(ts[i][k], u, acc[i]);
        }
        __syncthreads();
    }
    float bav = ba[h];
    #pragma unroll
    for (int i = 0; i < 8; i++) uh[(b0 + i) * Hz + h] = acc[i] + bav;
}

// ---------------------------------------------------------------------------
// Kernel 2: bf16 HMMA score GEMM + fused tanh·Va epilogue.
// CTA: 128 threads = 4 warps (2M x 2N), warp tile 64x64, CTA tile 128x128.
// K=2048 in 32 chunks of 64; 3-stage smem (96KB) -> 2 CTAs/SM.
// A: LDG fp32 -> cvt -> STS (reg staged);  B: cp.async bf16 direct.
// ---------------------------------------------------------------------------
#define ABUF(s) ((uint32_t)(s) * 16384u)            // 3 x 16KB
#define BBUF(s) (49152u + (uint32_t)(s) * 16384u)   // 3 x 16KB
#define SM_TOTAL 98304
#define NCHUNK 32

__global__ __launch_bounds__(128, 2)
void score_hmma_kernel(const float* __restrict__ frames,
                       const __nv_bfloat16* __restrict__ WaT,
                       const float* __restrict__ uh,
                       const float* __restrict__ Va,
                       float* __restrict__ partial) {
    extern __shared__ char smem[];
    const uint32_t sbase = smem_u32(smem);
    const int tid = threadIdx.x;
    const int wid = tid >> 5, lane = tid & 31;
    const int warp_m = wid & 1, warp_n = wid >> 1;    // 2 x 2
    const int wm = warp_m * 64, wn = warp_n * 64;
    const int h0   = blockIdx.x * 128;
    const int row0 = blockIdx.y * 128;

    float acc[4][8][4];
    #pragma unroll
    for (int i = 0; i < 4; i++)
        #pragma unroll
        for (int j = 0; j < 8; j++)
            #pragma unroll
            for (int e = 0; e < 4; e++) acc[i][j][e] = 0.f;

    float4 pa[16];   // A chunk staging: 128 rows x 64 fp32 / 128 threads

    // A global -> regs for chunk c
    auto loadGA = [&](int c) {
        const float* fA = frames + (size_t)row0 * Dz + c * 64;
        #pragma unroll
        for (int v = 0; v < 16; v++) {
            int idx = tid + v * 128;          // 128 rows x 16 float4
            int r = idx >> 4, c4 = (idx & 15) << 2;
            pa[v] = *(const float4*)(fA + (size_t)r * Dz + c4);
        }
    };
    // A regs -> smem stage s (cvt to bf16, swizzled)
    auto storeSA = [&](int s) {
        const uint32_t aoff = ABUF(s);
        #pragma unroll
        for (int v = 0; v < 16; v++) {
            int idx = tid + v * 128;
            int r = idx >> 4, c4 = (idx & 15) << 2;
            __nv_bfloat162 p0 = __floats2bfloat162_rn(pa[v].x, pa[v].y);
            __nv_bfloat162 p1 = __floats2bfloat162_rn(pa[v].z, pa[v].w);
            uint2 pk;
            pk.x = *(uint32_t*)&p0;
            pk.y = *(uint32_t*)&p1;
            *(uint2*)(smem + aoff + SWZ((uint32_t)(r * 128 + c4 * 2))) = pk;
        }
    };
    // B global -> smem stage s via cp.async (bf16 direct)
    auto cpB = [&](int c, int s) {
        const __nv_bfloat16* fB = WaT + (size_t)h0 * Dz + c * 64;
        const uint32_t boff = BBUF(s);
        #pragma unroll
        for (int v = 0; v < 8; v++) {
            int idx = tid + v * 128;          // 128 rows x 8 x16B
            int n = idx >> 3, k8 = (idx & 7) << 3;
            cp16(sbase + boff + SWZ((uint32_t)(n * 128 + k8 * 2)),
                 fB + (size_t)n * Dz + k8);
        }
    };
    // compute on stage s: 4 k16-steps, warp tile 64x64
    auto compute = [&](int s) {
        const uint32_t aoff = ABUF(s), boff = BBUF(s);
        #pragma unroll
        for (int ks = 0; ks < 4; ks++) {
            const int k16 = ks * 16;
            uint32_t bfr[8][2];
            #pragma unroll
            for (int jj = 0; jj < 4; jj++) {
                uint32_t r4[4];
                int g = lane >> 3;
                uint32_t off = (uint32_t)((wn + jj * 16 + (g >> 1) * 8 + (lane & 7)) * 128 +
                                          (k16 + (g & 1) * 8) * 2);
                ldsm4(r4, sbase + boff + SWZ(off));
                bfr[jj * 2 + 0][0] = r4[0]; bfr[jj * 2 + 0][1] = r4[1];
                bfr[jj * 2 + 1][0] = r4[2]; bfr[jj * 2 + 1][1] = r4[3];
            }
            #pragma unroll
            for (int i = 0; i < 4; i++) {
                uint32_t afr[4];
                uint32_t off = (uint32_t)((wm + i * 16 + (lane & 15)) * 128 +
                                          (k16 + (lane >> 4) * 8) * 2);
                ldsm4(afr, sbase + aoff + SWZ(off));
                #pragma unroll
                for (int j = 0; j < 8; j++)
                    mma16816(acc[i][j], afr, bfr[j]);
            }
        }
    };

    // Prologue: A0 stored; B0,B1 in flight; A1 staged in regs
    loadGA(0);
    storeSA(0);
    cpB(0, 0); CP_COMMIT();
    loadGA(1);
    cpB(1, 1); CP_COMMIT();

    for (int i = 0; i < NCHUNK; i++) {
        if (i < NCHUNK - 2) { CP_WAIT(1); } else { CP_WAIT(0); }
        __syncthreads();   // B stage i landed; A stage i visible; (i+2)%3 free
        if (i + 1 < NCHUNK) storeSA((i + 1) % 3);     // pa holds chunk i+1
        if (i + 2 < NCHUNK) {
            loadGA(i + 2);
            cpB(i + 2, (i + 2) % 3); CP_COMMIT();
        }
        compute(i % 3);
    }

    // ---- epilogue: tanh + Va-weighted sum over this CTA's 128 h-cols ----
    const int b = row0 >> 9;
    float va_r[16], uh_r[16];
    #pragma unroll
    for (int j = 0; j < 8; j++) {
        int col = h0 + wn + j * 8 + (lane & 3) * 2;
        va_r[j * 2 + 0] = __ldg(Va + col);
        va_r[j * 2 + 1] = __ldg(Va + col + 1);
        uh_r[j * 2 + 0] = __ldg(uh + b * Hz + col);
        uh_r[j * 2 + 1] = __ldg(uh + b * Hz + col + 1);
    }
    __syncthreads();
    float* red = (float*)smem;    // [128][2] overlay

    #pragma unroll
    for (int i = 0; i < 4; i++) {
        float s0 = 0.f, s1 = 0.f;
        #pragma unroll
        for (int j = 0; j < 8; j++) {
            s0 = fmaf(va_r[j*2+0], tanh_fast(acc[i][j][0] + uh_r[j*2+0]), s0);
            s0 = fmaf(va_r[j*2+1], tanh_fast(acc[i][j][1] + uh_r[j*2+1]), s0);
            s1 = fmaf(va_r[j*2+0], tanh_fast(acc[i][j][2] + uh_r[j*2+0]), s1);
            s1 = fmaf(va_r[j*2+1], tanh_fast(acc[i][j][3] + uh_r[j*2+1]), s1);
        }
        s0 += __shfl_xor_sync(0xffffffffu, s0, 1);
        s0 += __shfl_xor_sync(0xffffffffu, s0, 2);
        s1 += __shfl_xor_sync(0xffffffffu, s1, 1);
        s1 += __shfl_xor_sync(0xffffffffu, s1, 2);
        if ((lane & 3) == 0) {
            int r = wm + i * 16 + (lane >> 2);
            red[r * 2 + warp_n] = s0;
            red[(r + 8) * 2 + warp_n] = s1;
        }
    }
    __syncthreads();
    if (tid < 128) {
        float s = red[tid * 2] + red[tid * 2 + 1];
        partial[(size_t)blockIdx.x * BT + row0 + tid] = s;
    }
}

// ---------------------------------------------------------------------------
// Kernel 3: sum partials + softmax over T. One block per b, 512 threads.
// ---------------------------------------------------------------------------
__global__ __launch_bounds__(512)
void softmax_kernel(const float* __restrict__ partial,
                    float* __restrict__ att) {
    const int b = blockIdx.x;
    const int t = threadIdx.x;
    float s = 0.f;
    #pragma unroll
    for (int p = 0; p < NBLK; p++)
        s += partial[(size_t)p * BT + b * Tz + t];

    __shared__ float red[Tz];
    red[t] = s;
    __syncthreads();
    for (int off = 256; off; off >>= 1) {
        if (t < off) red[t] = fmaxf(red[t], red[t + off]);
        __syncthreads();
    }
    float m = red[0];
    __syncthreads();
    float e = expf(s - m);
    red[t] = e;
    __syncthreads();
    for (int off = 256; off; off >>= 1) {
        if (t < off) red[t] += red[t + off];
        __syncthreads();
    }
    att[b * Tz + t] = e * (1.0f / red[0]);
}

// ---------------------------------------------------------------------------
// Kernel 4: wsum (4-way T split) + combine
// ---------------------------------------------------------------------------
__global__ __launch_bounds__(256)
void wsum_kernel(const float* __restrict__ frames,
                 const float* __restrict__ att,
                 float* __restrict__ wpart) {
    const int b = blockIdx.y, sp = blockIdx.z;
    const int d = (blockIdx.x * 256 + threadIdx.x) * 4;
    const int t0 = sp * 128;

    __shared__ float as[128];
    if (threadIdx.x < 128) as[threadIdx.x] = att[b * Tz + t0 + threadIdx.x];
    __syncthreads();

    const float* fb = frames + ((size_t)b * Tz + t0) * Dz + d;
    float4 a0 = {0,0,0,0}, a1 = {0,0,0,0}, a2 = {0,0,0,0}, a3 = {0,0,0,0};
    #pragma unroll 2
    for (int t = 0; t < 128; t += 4) {
        float4 f0 = *(const float4*)(fb + (size_t)(t + 0) * Dz);
        float4 f1 = *(const float4*)(fb + (size_t)(t + 1) * Dz);
        float4 f2 = *(const float4*)(fb + (size_t)(t + 2) * Dz);
        float4 f3 = *(const float4*)(fb + (size_t)(t + 3) * Dz);
        float w0 = as[t], w1 = as[t + 1], w2 = as[t + 2], w3 = as[t + 3];
        a0.x = fmaf(w0, f0.x, a0.x); a0.y = fmaf(w0, f0.y, a0.y);
        a0.z = fmaf(w0, f0.z, a0.z); a0.w = fmaf(w0, f0.w, a0.w);
        a1.x = fmaf(w1, f1.x, a1.x); a1.y = fmaf(w1, f1.y, a1.y);
        a1.z = fmaf(w1, f1.z, a1.z); a1.w = fmaf(w1, f1.w, a1.w);
        a2.x = fmaf(w2, f2.x, a2.x); a2.y = fmaf(w2, f2.y, a2.y);
        a2.z = fmaf(w2, f2.z, a2.z); a2.w = fmaf(w2, f2.w, a2.w);
        a3.x = fmaf(w3, f3.x, a3.x); a3.y = fmaf(w3, f3.y, a3.y);
        a3.z = fmaf(w3, f3.z, a3.z); a3.w = fmaf(w3, f3.w, a3.w);
    }
    float4 r;
    r.x = (a0.x + a1.x) + (a2.x + a3.x);
    r.y = (a0.y + a1.y) + (a2.y + a3.y);
    r.z = (a0.z + a1.z) + (a2.z + a3.z);
    r.w = (a0.w + a1.w) + (a2.w + a3.w);
    *(float4*)(wpart + (size_t)sp * (Bz * Dz) + b * Dz + d) = r;
}

__global__ __launch_bounds__(256)
void wsum_combine(const float* __restrict__ wpart, float* __restrict__ out) {
    const int i = (blockIdx.x * 256 + threadIdx.x) * 4;
    float4 a = *(const float4*)(wpart + i);
    float4 b4 = *(const float4*)(wpart + 1 * (Bz * Dz) + i);
    float4 c = *(const float4*)(wpart + 2 * (Bz * Dz) + i);
    float4 d4 = *(const float4*)(wpart + 3 * (Bz * Dz) + i);
    float4 r;
    r.x = (a.x + b4.x) + (c.x + d4.x);
    r.y = (a.y + b4.y) + (c.y + d4.y);
    r.z = (a.z + b4.z) + (c.z + d4.z);
    r.w = (a.w + b4.w) + (c.w + d4.w);
    *(float4*)(out + i) = r;
}

// ---------------------------------------------------------------------------
extern "C" void kernel_launch(void* const* d_in, const int* in_sizes, int n_in,
                              void* d_out, int out_size) {
    const float* frames = (const float*)d_in[0];
    const float* text   = (const float*)d_in[1];
    const float* Wa     = (const float*)d_in[2];
    const float* Ua     = (const float*)d_in[3];
    const float* Va     = (const float*)d_in[4];
    const float* ba     = (const float*)d_in[5];
    float* out          = (float*)d_out;

    float *uh, *partial, *att, *wpart;
    __nv_bfloat16* WaT;
    cudaGetSymbolAddress((void**)&uh, g_uh);
    cudaGetSymbolAddress((void**)&partial, g_partial);
    cudaGetSymbolAddress((void**)&att, g_att);
    cudaGetSymbolAddress((void**)&WaT, g_WaT);
    cudaGetSymbolAddress((void**)&wpart, g_wpart);

    cudaFuncSetAttribute(score_hmma_kernel,
                         cudaFuncAttributeMaxDynamicSharedMemorySize, SM_TOTAL);

    transpose_kernel<<<dim3(Dz / 32, Hz / 32), dim3(32, 8)>>>(Wa, WaT);
    uh_kernel<<<dim3(Hz / 128, Bz / 8), 128>>>(text, Ua, ba, uh);
    // grid: x = h-block (4), y = row-block (256) -> A-tile L2 reuse
    score_hmma_kernel<<<dim3(NBLK, BT / 128), 128, SM_TOTAL>>>(
        frames, WaT, uh, Va, partial);
    softmax_kernel<<<Bz, Tz>>>(partial, att);
    wsum_kernel<<<dim3(2, Bz, 4), 256>>>(frames, att, wpart);
    wsum_combine<<<(Bz * Dz) / 1024, 256>>>(wpart, out);
}